// round 16
// baseline (speedup 1.0000x reference)
#include <cuda_runtime.h>
#include <cuda_bf16.h>
#include <math.h>
#include <cstdint>

// ---------------- problem constants ----------------
constexpr int Bc = 2, Sc = 1024, Dc = 1024, Hc = 16, Lc = 9, Wc = 1024, Pc = 128, Vc = 256;
constexpr int DH = Dc / Hc;          // 64
constexpr int BS = Bc * Sc;          // 2048 rows

typedef unsigned long long ull;
typedef __nv_bfloat16 bf16;

// ---------------- device scratch ----------------
__device__ float g_x [BS * Dc];
__device__ int   g_pidx[BS];

constexpr long OFF_SAIN  = 0;
constexpr long OFF_SAOUT = OFF_SAIN  + (long)Lc * 3 * Dc * Dc;
constexpr long OFF_CAIN  = OFF_SAOUT + (long)Lc * Dc * Dc;
constexpr long OFF_CAOUT = OFF_CAIN  + (long)Lc * 3 * Dc * Dc;
constexpr long OFF_FFN1  = OFF_CAOUT + (long)Lc * Dc * Dc;
constexpr long OFF_FFN2  = OFF_FFN1  + (long)Lc * 4 * Dc * Dc;
constexpr long OFF_OUTW  = OFF_FFN2  + (long)Lc * 4 * Dc * Dc;
constexpr long W_TOTAL   = OFF_OUTW  + (long)Vc * Dc;

__device__ bf16 g_whi[W_TOTAL];
__device__ bf16 g_wlo[W_TOTAL];

__device__ bf16 g_hh [BS * Dc],          g_hl [BS * Dc];
__device__ bf16 g_qh [BS * 3 * Dc],      g_ql [BS * 3 * Dc];
__device__ bf16 g_cqh[BS * Dc],          g_cql[BS * Dc];
__device__ bf16 g_ckh[Bc * Pc * 2 * Dc], g_ckl[Bc * Pc * 2 * Dc];
__device__ bf16 g_fh [BS * 4 * Dc],      g_fl [BS * 4 * Dc];
__device__ bf16 g_prh[Bc * Pc * Dc],     g_prl[Bc * Pc * Dc];

// ---------------- reductions ----------------
__device__ __forceinline__ float block_sum(float v) {
    __shared__ float sh[32];
    int lane = threadIdx.x & 31, w = threadIdx.x >> 5;
    int nw = blockDim.x >> 5;
    #pragma unroll
    for (int o = 16; o; o >>= 1) v += __shfl_xor_sync(0xffffffffu, v, o);
    __syncthreads();
    if (lane == 0) sh[w] = v;
    __syncthreads();
    if (threadIdx.x == 0) {
        float t = 0.f;
        for (int i = 0; i < nw; i++) t += sh[i];
        sh[0] = t;
    }
    __syncthreads();
    return sh[0];
}

// ================= helpers =================
__device__ __forceinline__ uint32_t s2u(const void* p) {
    return (uint32_t)__cvta_generic_to_shared(p);
}
__device__ __forceinline__ void cp16(uint32_t dst, const void* src) {
    asm volatile("cp.async.cg.shared.global [%0], [%1], 16;" :: "r"(dst), "l"(src));
}
__device__ __forceinline__ void cpwait1() {
    asm volatile("cp.async.wait_group 1;");
}
__device__ __forceinline__ void cpwait0() {
    asm volatile("cp.async.wait_group 0;");
}

#define LDSM4(R, addr) \
    asm volatile("ldmatrix.sync.aligned.m8n8.x4.shared.b16 {%0,%1,%2,%3}, [%4];" \
        : "=r"((R)[0]), "=r"((R)[1]), "=r"((R)[2]), "=r"((R)[3]) : "r"(addr))

#define LDSM4T(R, addr) \
    asm volatile("ldmatrix.sync.aligned.m8n8.x4.trans.shared.b16 {%0,%1,%2,%3}, [%4];" \
        : "=r"((R)[0]), "=r"((R)[1]), "=r"((R)[2]), "=r"((R)[3]) : "r"(addr))

#define MMA16816(d, a, b0, b1) \
    asm volatile("mma.sync.aligned.m16n8k16.row.col.f32.bf16.bf16.f32 " \
        "{%0,%1,%2,%3}, {%4,%5,%6,%7}, {%8,%9}, {%0,%1,%2,%3};" \
        : "+f"((d)[0]), "+f"((d)[1]), "+f"((d)[2]), "+f"((d)[3]) \
        : "r"((a)[0]), "r"((a)[1]), "r"((a)[2]), "r"((a)[3]), "r"(b0), "r"(b1))

__device__ __forceinline__ void split2(float x0, float x1, uint32_t& h, uint32_t& l) {
    __nv_bfloat162 hh = __floats2bfloat162_rn(x0, x1);
    float2 hf = __bfloat1622float2(hh);
    __nv_bfloat162 ll = __floats2bfloat162_rn(x0 - hf.x, x1 - hf.y);
    h = *(uint32_t*)&hh; l = *(uint32_t*)&ll;
}

// ================= pipelined bf16x3 mma.sync GEMM (A @ B^T), lookahead-2 =================
constexpr int RS = 40;
constexpr int tcs_bytes(int BM) { return 2 * (2 * BM + 2 * 128) * RS * 2; }

template<int EPI, bool OUTBF, int BM>
__global__ __launch_bounds__(128, (BM == 64 ? 3 : 2))
void gemm_tc(const bf16* __restrict__ Ah, const bf16* __restrict__ Al, int lda, long hiA, long loA, int nloA,
             const bf16* __restrict__ Bh, const bf16* __restrict__ Bl, int ldb, long hiB, long loB, int nloB,
             const float* __restrict__ bias, const float* __restrict__ Res,
             float* __restrict__ C, bf16* __restrict__ Chi, bf16* __restrict__ Clo,
             int ldc, long hiC, long loC, int nloC, int K, float scale)
{
    extern __shared__ __align__(16) bf16 sbuf[];

    constexpr int MT = BM / 32;
    constexpr int TPR = 128 / BM;
    constexpr int QA = BM / 32;
    constexpr int STAGE_E = (2 * BM + 2 * 128) * RS;

    const int m0 = blockIdx.y * BM, n0 = blockIdx.x * 128;

    const int tid = threadIdx.x, lane = tid & 31, wid = tid >> 5;
    const int wm = wid >> 1, wn = wid & 1;
    const int z = blockIdx.z;
    Ah += (long)(z / nloA) * hiA + (long)(z % nloA) * loA;
    Al += (long)(z / nloA) * hiA + (long)(z % nloA) * loA;
    Bh += (long)(z / nloB) * hiB + (long)(z % nloB) * loB;
    Bl += (long)(z / nloB) * hiB + (long)(z % nloB) * loB;
    const long coff = (long)(z / nloC) * hiC + (long)(z % nloC) * loC;

    const uint32_t sbase = s2u(sbuf);

    const int arow = tid / TPR;
    const int akoff = (tid % TPR) * 16;
    const bf16* pAh = Ah + (size_t)(m0 + arow) * lda + akoff;
    const bf16* pAl = Al + (size_t)(m0 + arow) * lda + akoff;
    const bf16* pBh = Bh + (size_t)(n0 + tid) * ldb;
    const bf16* pBl = Bl + (size_t)(n0 + tid) * ldb;

    float acc[MT][8][4];
    #pragma unroll
    for (int i = 0; i < MT; i++)
        #pragma unroll
        for (int j = 0; j < 8; j++)
            #pragma unroll
            for (int q = 0; q < 4; q++) acc[i][j][q] = 0.f;

    const int nk = K / 32;

    auto issue = [&](int c) {
        uint32_t base = sbase + (uint32_t)(c & 1) * (STAGE_E * 2);
        {
            uint32_t dst = base + (uint32_t)(arow * RS + akoff) * 2;
            const bf16* sa = pAh + c * 32;
            const bf16* sl = pAl + c * 32;
            #pragma unroll
            for (int q = 0; q < QA; q++) {
                cp16(dst + q * 16, sa + q * 8);
                cp16(dst + BM * RS * 2 + q * 16, sl + q * 8);
            }
        }
        {
            uint32_t dst = base + (uint32_t)(2 * BM * RS + tid * RS) * 2;
            const bf16* sb = pBh + c * 32;
            const bf16* sl = pBl + c * 32;
            #pragma unroll
            for (int q = 0; q < 4; q++) {
                cp16(dst + q * 16, sb + q * 8);
                cp16(dst + 128 * RS * 2 + q * 16, sl + q * 8);
            }
        }
        asm volatile("cp.async.commit_group;");
    };

    issue(0);
    if (nk > 1) issue(1);

    const int lrow = lane & 15, lko = (lane >> 4) * 8;

    for (int k0 = 0; k0 < nk; k0++) {
        if (k0 + 1 < nk) cpwait1(); else cpwait0();
        __syncthreads();

        const bf16* bAh = sbuf + (size_t)(k0 & 1) * STAGE_E;
        const bf16* bAl = bAh + BM * RS;
        const bf16* bBh = bAh + 2 * BM * RS;
        const bf16* bBl = bBh + 128 * RS;

        #pragma unroll
        for (int kk = 0; kk < 32; kk += 16) {
            uint32_t Afh[MT][4], Afl[MT][4];
            #pragma unroll
            for (int mt = 0; mt < MT; mt++)
                LDSM4(Afh[mt], s2u(&bAh[(wm * (BM / 2) + mt * 16 + lrow) * RS + kk + lko]));
            #pragma unroll
            for (int mt = 0; mt < MT; mt++)
                LDSM4(Afl[mt], s2u(&bAl[(wm * (BM / 2) + mt * 16 + lrow) * RS + kk + lko]));

            #pragma unroll
            for (int p = 0; p < 4; p++) {
                uint32_t Bfh[4], Bfl[4];
                LDSM4(Bfh, s2u(&bBh[(wn * 64 + p * 16 + lrow) * RS + kk + lko]));
                LDSM4(Bfl, s2u(&bBl[(wn * 64 + p * 16 + lrow) * RS + kk + lko]));
                #pragma unroll
                for (int mt = 0; mt < MT; mt++) {
                    MMA16816(acc[mt][2 * p + 0], Afh[mt], Bfh[0], Bfh[2]);
                    MMA16816(acc[mt][2 * p + 1], Afh[mt], Bfh[1], Bfh[3]);
                    MMA16816(acc[mt][2 * p + 0], Afh[mt], Bfl[0], Bfl[2]);
                    MMA16816(acc[mt][2 * p + 1], Afh[mt], Bfl[1], Bfl[3]);
                    MMA16816(acc[mt][2 * p + 0], Afl[mt], Bfh[0], Bfh[2]);
                    MMA16816(acc[mt][2 * p + 1], Afl[mt], Bfh[1], Bfh[3]);
                }
            }
        }

        __syncthreads();
        if (k0 + 2 < nk) issue(k0 + 2);
    }

    float* Cb = C ? (C + coff) : nullptr;
    const float* Rb = (EPI == 3) ? (Res + coff) : nullptr;
    bf16* Hb = OUTBF ? (Chi + coff) : nullptr;
    bf16* Lb = OUTBF ? (Clo + coff) : nullptr;
    const int rb = lane >> 2, cbl = (lane & 3) * 2;
    #pragma unroll
    for (int mt = 0; mt < MT; mt++) {
        #pragma unroll
        for (int half = 0; half < 2; half++) {
            int r = m0 + wm * (BM / 2) + mt * 16 + rb + half * 8;
            #pragma unroll
            for (int j = 0; j < 8; j++) {
                int cc = n0 + wn * 64 + (j >> 1) * 16 + (j & 1) * 8 + cbl;
                float x0 = acc[mt][j][half * 2 + 0] * scale;
                float x1 = acc[mt][j][half * 2 + 1] * scale;
                if (EPI >= 1) { x0 += bias[cc]; x1 += bias[cc + 1]; }
                if (EPI == 2) {
                    x0 = 0.5f * x0 * (1.f + erff(x0 * 0.70710678118654752f));
                    x1 = 0.5f * x1 * (1.f + erff(x1 * 0.70710678118654752f));
                }
                if (EPI == 3) {
                    float2 rv = *(const float2*)(Rb + (size_t)r * ldc + cc);
                    x0 += rv.x; x1 += rv.y;
                }
                if (Cb) *(float2*)(Cb + (size_t)r * ldc + cc) = make_float2(x0, x1);
                if (OUTBF) {
                    uint32_t h, l;
                    split2(x0, x1, h, l);
                    *(uint32_t*)(Hb + (size_t)r * ldc + cc) = h;
                    *(uint32_t*)(Lb + (size_t)r * ldc + cc) = l;
                }
            }
        }
    }
}

// ================= fused flash attention (128-row Q blocks, 256 threads, lookahead-2) =================
constexpr int FR = 72;
constexpr int FQE = 2 * 128 * FR;
constexpr int FSTE = 4 * 64 * FR;
constexpr int FSZ = (FQE + 2 * FSTE) * 2;

template<int MASK>
__global__ __launch_bounds__(256, 2)
void flash_att(const bf16* __restrict__ Qh, const bf16* __restrict__ Ql, int ldq, long hiQ, long loQ,
               const bf16* __restrict__ Kh, const bf16* __restrict__ Kl,
               const bf16* __restrict__ Vh, const bf16* __restrict__ Vl, int ldk, long hiK, long loK,
               const int* __restrict__ pidx,
               bf16* __restrict__ Ohp, bf16* __restrict__ Olp, int ldo, long hiO, long loO,
               int nKeys)
{
    extern __shared__ __align__(16) bf16 sbuf[];

    const int tid = threadIdx.x, lane = tid & 31, wid = tid >> 5;
    const int z = blockIdx.y;
    const int m0 = ((int)gridDim.x - 1 - (int)blockIdx.x) * 128;   // heavy-first
    const int b = z / Hc;

    const long qoff = (long)(z / Hc) * hiQ + (long)(z % Hc) * loQ;
    const long koff = (long)(z / Hc) * hiK + (long)(z % Hc) * loK;
    const long ooff = (long)(z / Hc) * hiO + (long)(z % Hc) * loO;

    const bf16* pQh = Qh + qoff;
    const bf16* pQl = Ql + qoff;
    const bf16* pKh = Kh + koff;
    const bf16* pKl = Kl + koff;
    const bf16* pVh = Vh + koff;
    const bf16* pVl = Vl + koff;

    const uint32_t sbase = s2u(sbuf);

    const int qrow = tid >> 1, qhalf = (tid & 1) * 32;
    {
        uint32_t dq = sbase + (uint32_t)(qrow * FR + qhalf) * 2;
        const bf16* sq = pQh + (size_t)(m0 + qrow) * ldq + qhalf;
        const bf16* sl = pQl + (size_t)(m0 + qrow) * ldq + qhalf;
        #pragma unroll
        for (int q = 0; q < 4; q++) {
            cp16(dq + q * 16, sq + q * 8);
            cp16(dq + 128 * FR * 2 + q * 16, sl + q * 8);
        }
    }

    const int kvrow = tid >> 2, kvq = (tid & 3) * 16;
    auto issueKV = [&](int jb) {
        uint32_t base = sbase + (uint32_t)(FQE + (jb & 1) * FSTE) * 2;
        const bf16* srcs[4];
        srcs[0] = pKh + (size_t)(jb * 64 + kvrow) * ldk + kvq;
        srcs[1] = pKl + (size_t)(jb * 64 + kvrow) * ldk + kvq;
        srcs[2] = pVh + (size_t)(jb * 64 + kvrow) * ldk + kvq;
        srcs[3] = pVl + (size_t)(jb * 64 + kvrow) * ldk + kvq;
        #pragma unroll
        for (int t = 0; t < 4; t++) {
            uint32_t dst = base + (uint32_t)(t * 64 * FR + kvrow * FR + kvq) * 2;
            #pragma unroll
            for (int q = 0; q < 2; q++)
                cp16(dst + q * 16, srcs[t] + q * 8);
        }
        asm volatile("cp.async.commit_group;");
    };

    int nb;
    if (MASK == 0) {
        nb = m0 / 64 + 2;
        int nbmax = nKeys / 64;
        if (nb > nbmax) nb = nbmax;
    } else {
        nb = nKeys / 64;
    }

    issueKV(0);
    if (nb > 1) issueKV(1);

    const int gr0 = m0 + wid * 16 + (lane >> 2);
    int lim0, lim1;
    if (MASK == 0) { lim0 = gr0; lim1 = gr0 + 8; }
    else           { lim0 = pidx[b * Sc + gr0]; lim1 = pidx[b * Sc + gr0 + 8]; }

    float o[8][4];
    #pragma unroll
    for (int g = 0; g < 8; g++)
        #pragma unroll
        for (int q = 0; q < 4; q++) o[g][q] = 0.f;
    float mr0 = -1e30f, mr1 = -1e30f, lr0 = 0.f, lr1 = 0.f;

    const int lrow = lane & 15, lko = (lane >> 4) * 8;
    const int tkrow = (lane & 7) + ((lane >> 4) << 3);
    const int tncol = ((lane >> 3) & 1) * 8;
    const int cbl = (lane & 3) * 2;

    for (int jb = 0; jb < nb; jb++) {
        if (jb + 1 < nb) cpwait1(); else cpwait0();
        __syncthreads();

        const bf16* sQh = sbuf;
        const bf16* sQl = sQh + 128 * FR;
        const bf16* sKh = sbuf + FQE + (size_t)(jb & 1) * FSTE;
        const bf16* sKl = sKh + 64 * FR;
        const bf16* sVh = sKh + 2 * 64 * FR;
        const bf16* sVl = sKh + 3 * 64 * FR;

        // ---- S = Q @ K^T (bf16x3)
        float s[8][4];
        #pragma unroll
        for (int g = 0; g < 8; g++)
            #pragma unroll
            for (int q = 0; q < 4; q++) s[g][q] = 0.f;

        #pragma unroll
        for (int kk = 0; kk < 64; kk += 16) {
            uint32_t qfh[4], qfl[4];
            LDSM4(qfh, s2u(&sQh[(wid * 16 + lrow) * FR + kk + lko]));
            LDSM4(qfl, s2u(&sQl[(wid * 16 + lrow) * FR + kk + lko]));
            #pragma unroll
            for (int p = 0; p < 4; p++) {
                uint32_t kfh[4], kfl[4];
                LDSM4(kfh, s2u(&sKh[(p * 16 + lrow) * FR + kk + lko]));
                LDSM4(kfl, s2u(&sKl[(p * 16 + lrow) * FR + kk + lko]));
                MMA16816(s[2 * p + 0], qfh, kfh[0], kfh[2]);
                MMA16816(s[2 * p + 1], qfh, kfh[1], kfh[3]);
                MMA16816(s[2 * p + 0], qfh, kfl[0], kfl[2]);
                MMA16816(s[2 * p + 1], qfh, kfl[1], kfl[3]);
                MMA16816(s[2 * p + 0], qfl, kfh[0], kfh[2]);
                MMA16816(s[2 * p + 1], qfl, kfh[1], kfh[3]);
            }
        }

        // ---- scale + mask
        const int jbase = jb * 64;
        #pragma unroll
        for (int g = 0; g < 8; g++) {
            #pragma unroll
            for (int q = 0; q < 4; q++) {
                int col = jbase + g * 8 + cbl + (q & 1);
                int lim = (q < 2) ? lim0 : lim1;
                float v = s[g][q] * 0.125f;
                s[g][q] = (col > lim) ? -1e30f : v;
            }
        }

        // ---- online softmax (fast exp)
        float mx0 = -1e30f, mx1 = -1e30f;
        #pragma unroll
        for (int g = 0; g < 8; g++) {
            mx0 = fmaxf(mx0, fmaxf(s[g][0], s[g][1]));
            mx1 = fmaxf(mx1, fmaxf(s[g][2], s[g][3]));
        }
        mx0 = fmaxf(mx0, __shfl_xor_sync(0xffffffffu, mx0, 1));
        mx0 = fmaxf(mx0, __shfl_xor_sync(0xffffffffu, mx0, 2));
        mx1 = fmaxf(mx1, __shfl_xor_sync(0xffffffffu, mx1, 1));
        mx1 = fmaxf(mx1, __shfl_xor_sync(0xffffffffu, mx1, 2));

        float nm0 = fmaxf(mr0, mx0), nm1 = fmaxf(mr1, mx1);
        float c0 = __expf(mr0 - nm0), c1 = __expf(mr1 - nm1);

        float sum0 = 0.f, sum1 = 0.f;
        #pragma unroll
        for (int g = 0; g < 8; g++) {
            s[g][0] = __expf(s[g][0] - nm0); sum0 += s[g][0];
            s[g][1] = __expf(s[g][1] - nm0); sum0 += s[g][1];
            s[g][2] = __expf(s[g][2] - nm1); sum1 += s[g][2];
            s[g][3] = __expf(s[g][3] - nm1); sum1 += s[g][3];
        }
        sum0 += __shfl_xor_sync(0xffffffffu, sum0, 1);
        sum0 += __shfl_xor_sync(0xffffffffu, sum0, 2);
        sum1 += __shfl_xor_sync(0xffffffffu, sum1, 1);
        sum1 += __shfl_xor_sync(0xffffffffu, sum1, 2);

        lr0 = lr0 * c0 + sum0;
        lr1 = lr1 * c1 + sum1;
        mr0 = nm0; mr1 = nm1;

        #pragma unroll
        for (int g = 0; g < 8; g++) {
            o[g][0] *= c0; o[g][1] *= c0;
            o[g][2] *= c1; o[g][3] *= c1;
        }

        // ---- O += P @ V
        #pragma unroll
        for (int t = 0; t < 4; t++) {
            uint32_t Pa_h[4], Pa_l[4];
            split2(s[2 * t][0],     s[2 * t][1],     Pa_h[0], Pa_l[0]);
            split2(s[2 * t][2],     s[2 * t][3],     Pa_h[1], Pa_l[1]);
            split2(s[2 * t + 1][0], s[2 * t + 1][1], Pa_h[2], Pa_l[2]);
            split2(s[2 * t + 1][2], s[2 * t + 1][3], Pa_h[3], Pa_l[3]);
            #pragma unroll
            for (int p = 0; p < 4; p++) {
                uint32_t vfh[4], vfl[4];
                LDSM4T(vfh, s2u(&sVh[(t * 16 + tkrow) * FR + p * 16 + tncol]));
                LDSM4T(vfl, s2u(&sVl[(t * 16 + tkrow) * FR + p * 16 + tncol]));
                MMA16816(o[2 * p + 0], Pa_h, vfh[0], vfh[2]);
                MMA16816(o[2 * p + 1], Pa_h, vfh[1], vfh[3]);
                MMA16816(o[2 * p + 0], Pa_h, vfl[0], vfl[2]);
                MMA16816(o[2 * p + 1], Pa_h, vfl[1], vfl[3]);
                MMA16816(o[2 * p + 0], Pa_l, vfh[0], vfh[2]);
                MMA16816(o[2 * p + 1], Pa_l, vfh[1], vfh[3]);
            }
        }

        __syncthreads();
        if (jb + 2 < nb) issueKV(jb + 2);
    }

    // ---- epilogue
    float inv0 = 1.f / lr0, inv1 = 1.f / lr1;
    bf16* Ob_h = Ohp + ooff;
    bf16* Ob_l = Olp + ooff;
    const int r0 = m0 + wid * 16 + (lane >> 2);
    #pragma unroll
    for (int g = 0; g < 8; g++) {
        int cc = g * 8 + cbl;
        uint32_t h, l;
        split2(o[g][0] * inv0, o[g][1] * inv0, h, l);
        *(uint32_t*)(Ob_h + (size_t)r0 * ldo + cc) = h;
        *(uint32_t*)(Ob_l + (size_t)r0 * ldo + cc) = l;
        split2(o[g][2] * inv1, o[g][3] * inv1, h, l);
        *(uint32_t*)(Ob_h + (size_t)(r0 + 8) * ldo + cc) = h;
        *(uint32_t*)(Ob_l + (size_t)(r0 + 8) * ldo + cc) = l;
    }
}

// ---------------- fp32 -> bf16 hi/lo conversion ----------------
__global__ void cvt_k(const float* __restrict__ x, bf16* __restrict__ hi,
                      bf16* __restrict__ lo, long n)
{
    long i = ((long)blockIdx.x * blockDim.x + threadIdx.x) * 4;
    if (i >= n) return;
    float4 v = *(const float4*)(x + i);
    uint32_t h0, l0, h1, l1;
    split2(v.x, v.y, h0, l0);
    split2(v.z, v.w, h1, l1);
    *(uint2*)(hi + i) = make_uint2(h0, h1);
    *(uint2*)(lo + i) = make_uint2(l0, l1);
}

// ---------------- embedding ----------------
__global__ void embed_k(const int* __restrict__ seq, const float* __restrict__ bemb,
                        const float* __restrict__ pemb, float* __restrict__ x)
{
    int r = blockIdx.x;
    int s = r % Sc;
    int tok = seq[r];
    int c = threadIdx.x * 4;
    float4 e = *(const float4*)(bemb + (long)tok * Dc + c);
    float4 p = *(const float4*)(pemb + (long)s * Dc + c);
    e.x += p.x; e.y += p.y; e.z += p.z; e.w += p.w;
    *(float4*)(x + (long)r * Dc + c) = e;
}

// ---------------- layernorm -> bf16 hi/lo planes ----------------
__global__ void ln_k(const float* __restrict__ x, const float* __restrict__ g,
                     const float* __restrict__ b, bf16* __restrict__ hi,
                     bf16* __restrict__ lo)
{
    const int row = blockIdx.x;
    const int tid = threadIdx.x;
    const float* xr = x + (long)row * Dc;
    float4 v = *(const float4*)(xr + tid * 4);
    float s = v.x + v.y + v.z + v.w;
    float tot = block_sum(s);
    float m = tot * (1.f / Dc);
    float dx0 = v.x - m, dx1 = v.y - m, dx2 = v.z - m, dx3 = v.w - m;
    float q = dx0 * dx0 + dx1 * dx1 + dx2 * dx2 + dx3 * dx3;
    float totq = block_sum(q);
    float rs = rsqrtf(totq * (1.f / Dc) + 1e-5f);
    float4 gg = *(const float4*)(g + tid * 4);
    float4 bb = *(const float4*)(b + tid * 4);
    float o0 = dx0 * rs * gg.x + bb.x;
    float o1 = dx1 * rs * gg.y + bb.y;
    float o2 = dx2 * rs * gg.z + bb.z;
    float o3 = dx3 * rs * gg.w + bb.w;
    uint32_t h0, l0, h1, l1;
    split2(o0, o1, h0, l0);
    split2(o2, o3, h1, l1);
    *(uint2*)(hi + (long)row * Dc + tid * 4) = make_uint2(h0, h1);
    *(uint2*)(lo + (long)row * Dc + tid * 4) = make_uint2(l0, l1);
}

// ---------------- inclusive cumsum ----------------
__global__ void cumsum_k(const int* __restrict__ bd, int* __restrict__ pidx)
{
    __shared__ int s[Sc];
    const int b = blockIdx.x, t = threadIdx.x;
    s[t] = bd[b * Sc + t];
    __syncthreads();
    for (int off = 1; off < Sc; off <<= 1) {
        int v = (t >= off) ? s[t - off] : 0;
        __syncthreads();
        s[t] += v;
        __syncthreads();
    }
    pidx[b * Sc + t] = s[t];
}

// ---------------- launcher ----------------
extern "C" void kernel_launch(void* const* d_in, const int* in_sizes, int n_in,
                              void* d_out, int out_size)
{
    const int*   byte_seq  = (const int*)  d_in[0];
    const float* patch_rep = (const float*)d_in[1];
    const int*   patch_bd  = (const int*)  d_in[2];
    const float* byte_emb  = (const float*)d_in[3];
    const float* pos_emb   = (const float*)d_in[4];
    const float* sa_in_w   = (const float*)d_in[5];
    const float* sa_in_b   = (const float*)d_in[6];
    const float* sa_out_w  = (const float*)d_in[7];
    const float* sa_out_b  = (const float*)d_in[8];
    const float* ca_in_w   = (const float*)d_in[9];
    const float* ca_in_b   = (const float*)d_in[10];
    const float* ca_out_w  = (const float*)d_in[11];
    const float* ca_out_b  = (const float*)d_in[12];
    const float* ffn_w1    = (const float*)d_in[13];
    const float* ffn_b1    = (const float*)d_in[14];
    const float* ffn_w2    = (const float*)d_in[15];
    const float* ffn_b2    = (const float*)d_in[16];
    const float* ln_g      = (const float*)d_in[17];
    const float* ln_b      = (const float*)d_in[18];
    const float* norm_g    = (const float*)d_in[19];
    const float* norm_b    = (const float*)d_in[20];
    const float* out_w     = (const float*)d_in[21];
    float* out = (float*)d_out;

    float* gx;
    int* gpidx;
    bf16 *whi, *wlo, *hh, *hl, *qh, *ql, *cqh, *cql, *ckh, *ckl, *fh, *fl, *prh, *prl;
    cudaGetSymbolAddress((void**)&gx,   g_x);
    cudaGetSymbolAddress((void**)&gpidx, g_pidx);
    cudaGetSymbolAddress((void**)&whi, g_whi);
    cudaGetSymbolAddress((void**)&wlo, g_wlo);
    cudaGetSymbolAddress((void**)&hh,  g_hh);
    cudaGetSymbolAddress((void**)&hl,  g_hl);
    cudaGetSymbolAddress((void**)&qh,  g_qh);
    cudaGetSymbolAddress((void**)&ql,  g_ql);
    cudaGetSymbolAddress((void**)&cqh, g_cqh);
    cudaGetSymbolAddress((void**)&cql, g_cql);
    cudaGetSymbolAddress((void**)&ckh, g_ckh);
    cudaGetSymbolAddress((void**)&ckl, g_ckl);
    cudaGetSymbolAddress((void**)&fh,  g_fh);
    cudaGetSymbolAddress((void**)&fl,  g_fl);
    cudaGetSymbolAddress((void**)&prh, g_prh);
    cudaGetSymbolAddress((void**)&prl, g_prl);

    constexpr int T128 = tcs_bytes(128);
    constexpr int T64  = tcs_bytes(64);
    cudaFuncSetAttribute(gemm_tc<1, true, 128>,  cudaFuncAttributeMaxDynamicSharedMemorySize, T128);
    cudaFuncSetAttribute(gemm_tc<2, true, 128>,  cudaFuncAttributeMaxDynamicSharedMemorySize, T128);
    cudaFuncSetAttribute(gemm_tc<0, false, 64>,  cudaFuncAttributeMaxDynamicSharedMemorySize, T64);
    cudaFuncSetAttribute(gemm_tc<1, true, 64>,   cudaFuncAttributeMaxDynamicSharedMemorySize, T64);
    cudaFuncSetAttribute(gemm_tc<3, false, 64>,  cudaFuncAttributeMaxDynamicSharedMemorySize, T64);
    cudaFuncSetAttribute(flash_att<0>, cudaFuncAttributeMaxDynamicSharedMemorySize, FSZ);
    cudaFuncSetAttribute(flash_att<1>, cudaFuncAttributeMaxDynamicSharedMemorySize, FSZ);

    auto cvt = [&](const float* src, bf16* dh, bf16* dl, long n) {
        cvt_k<<<(unsigned)((n / 4 + 255) / 256), 256>>>(src, dh, dl, n);
    };
    cvt(sa_in_w,  whi + OFF_SAIN,  wlo + OFF_SAIN,  (long)Lc * 3 * Dc * Dc);
    cvt(sa_out_w, whi + OFF_SAOUT, wlo + OFF_SAOUT, (long)Lc * Dc * Dc);
    cvt(ca_in_w,  whi + OFF_CAIN,  wlo + OFF_CAIN,  (long)Lc * 3 * Dc * Dc);
    cvt(ca_out_w, whi + OFF_CAOUT, wlo + OFF_CAOUT, (long)Lc * Dc * Dc);
    cvt(ffn_w1,   whi + OFF_FFN1,  wlo + OFF_FFN1,  (long)Lc * 4 * Dc * Dc);
    cvt(ffn_w2,   whi + OFF_FFN2,  wlo + OFF_FFN2,  (long)Lc * 4 * Dc * Dc);
    cvt(out_w,    whi + OFF_OUTW,  wlo + OFF_OUTW,  (long)Vc * Dc);
    cvt(patch_rep, prh, prl, (long)Bc * Pc * Dc);

    embed_k<<<BS, 256>>>(byte_seq, byte_emb, pos_emb, gx);
    cumsum_k<<<Bc, Sc>>>(patch_bd, gpidx);

    for (int l = 0; l < Lc; l++) {
        // ===== self-attention =====
        ln_k<<<BS, 256>>>(gx, ln_g + (long)(l * 3 + 0) * Dc, ln_b + (long)(l * 3 + 0) * Dc, hh, hl);

        gemm_tc<1, true, 128><<<dim3(3 * Dc / 128, BS / 128), 128, T128>>>(
            hh, hl, Dc, 0, 0, 1,
            whi + OFF_SAIN + (long)l * 3 * Dc * Dc, wlo + OFF_SAIN + (long)l * 3 * Dc * Dc, Dc, 0, 0, 1,
            sa_in_b + (long)l * 3 * Dc, nullptr,
            nullptr, qh, ql, 3 * Dc, 0, 0, 1, Dc, 1.f);

        flash_att<0><<<dim3(Sc / 128, Bc * Hc), 256, FSZ>>>(
            qh, ql, 3 * Dc, (long)Sc * 3 * Dc, DH,
            qh + Dc, ql + Dc, qh + 2 * Dc, ql + 2 * Dc, 3 * Dc, (long)Sc * 3 * Dc, DH,
            nullptr,
            cqh, cql, Dc, (long)Sc * Dc, DH, Sc);

        gemm_tc<3, false, 64><<<dim3(Dc / 128, BS / 64), 128, T64>>>(
            cqh, cql, Dc, 0, 0, 1,
            whi + OFF_SAOUT + (long)l * Dc * Dc, wlo + OFF_SAOUT + (long)l * Dc * Dc, Dc, 0, 0, 1,
            sa_out_b + (long)l * Dc, gx,
            gx, nullptr, nullptr, Dc, 0, 0, 1, Dc, 1.f);

        // ===== cross-attention =====
        ln_k<<<BS, 256>>>(gx, ln_g + (long)(l * 3 + 1) * Dc, ln_b + (long)(l * 3 + 1) * Dc, hh, hl);

        gemm_tc<1, true, 64><<<dim3(Dc / 128, BS / 64), 128, T64>>>(
            hh, hl, Dc, 0, 0, 1,
            whi + OFF_CAIN + (long)l * 3 * Dc * Dc, wlo + OFF_CAIN + (long)l * 3 * Dc * Dc, Dc, 0, 0, 1,
            ca_in_b + (long)l * 3 * Dc, nullptr,
            nullptr, cqh, cql, Dc, 0, 0, 1, Dc, 1.f);

        gemm_tc<1, true, 64><<<dim3(2 * Dc / 128, (Bc * Pc) / 64), 128, T64>>>(
            prh, prl, Dc, 0, 0, 1,
            whi + OFF_CAIN + (long)l * 3 * Dc * Dc + (long)Dc * Dc,
            wlo + OFF_CAIN + (long)l * 3 * Dc * Dc + (long)Dc * Dc, Dc, 0, 0, 1,
            ca_in_b + (long)l * 3 * Dc + Dc, nullptr,
            nullptr, ckh, ckl, 2 * Dc, 0, 0, 1, Dc, 1.f);

        flash_att<1><<<dim3(Sc / 128, Bc * Hc), 256, FSZ>>>(
            cqh, cql, Dc, (long)Sc * Dc, DH,
            ckh, ckl, ckh + Dc, ckl + Dc, 2 * Dc, (long)Pc * 2 * Dc, DH,
            gpidx,
            cqh, cql, Dc, (long)Sc * Dc, DH, Pc);

        gemm_tc<3, false, 64><<<dim3(Dc / 128, BS / 64), 128, T64>>>(
            cqh, cql, Dc, 0, 0, 1,
            whi + OFF_CAOUT + (long)l * Dc * Dc, wlo + OFF_CAOUT + (long)l * Dc * Dc, Dc, 0, 0, 1,
            ca_out_b + (long)l * Dc, gx,
            gx, nullptr, nullptr, Dc, 0, 0, 1, Dc, 1.f);

        // ===== FFN =====
        ln_k<<<BS, 256>>>(gx, ln_g + (long)(l * 3 + 2) * Dc, ln_b + (long)(l * 3 + 2) * Dc, hh, hl);

        gemm_tc<2, true, 128><<<dim3(4 * Dc / 128, BS / 128), 128, T128>>>(
            hh, hl, Dc, 0, 0, 1,
            whi + OFF_FFN1 + (long)l * 4 * Dc * Dc, wlo + OFF_FFN1 + (long)l * 4 * Dc * Dc, Dc, 0, 0, 1,
            ffn_b1 + (long)l * 4 * Dc, nullptr,
            nullptr, fh, fl, 4 * Dc, 0, 0, 1, Dc, 1.f);

        gemm_tc<3, false, 64><<<dim3(Dc / 128, BS / 64), 128, T64>>>(
            fh, fl, 4 * Dc, 0, 0, 1,
            whi + OFF_FFN2 + (long)l * Dc * 4 * Dc, wlo + OFF_FFN2 + (long)l * Dc * 4 * Dc, 4 * Dc, 0, 0, 1,
            ffn_b2 + (long)l * Dc, gx,
            gx, nullptr, nullptr, Dc, 0, 0, 1, 4 * Dc, 1.f);
    }

    // final LN + vocab projection
    ln_k<<<BS, 256>>>(gx, norm_g, norm_b, hh, hl);
    gemm_tc<0, false, 64><<<dim3(Vc / 128, BS / 64), 128, T64>>>(
        hh, hl, Dc, 0, 0, 1,
        whi + OFF_OUTW, wlo + OFF_OUTW, Dc, 0, 0, 1,
        nullptr, nullptr,
        out, nullptr, nullptr, Vc, 0, 0, 1, Dc, 1.f);
}